// round 16
// baseline (speedup 1.0000x reference)
#include <cuda_runtime.h>
#include <cuda_fp16.h>

#define N_ 32
#define C_ 3
#define H_ 224
#define W_ 224
#define S_ 17            // thetas per batch
#define HPT 16           // h-rows per thread (vertical chain, corner reuse)

#define HQ (H_ / HPT)                 // 14 row-groups
#define THREADS W_                    // 224 = 7 warps; warp = 32 consecutive w at one h
#define NBLOCKS (N_ * S_ * HQ)        // 7616

// padded pair grid: x,y in [-2, 225] -> 228 x 228 entries
#define PW 228
#define PH 228
#define NPAIR (N_ * PH * PW)          // 26.6 MB

// g_pair[n][py][px] = uint4{ h2(c0_x,c0_x1), h2(c1_x,c1_x1), h2(c2_x,c2_x1), 0 }
// where x = px-2; OOB pixels stored as 0.
__device__ uint4 g_pair[NPAIR];

static __device__ __forceinline__ unsigned h2u(float a, float b)
{
    __half2 h = __floats2half2_rn(a, b);
    return *reinterpret_cast<unsigned*>(&h);
}

static __device__ __forceinline__ float2 u2f(unsigned u)
{
    __half2 h = *reinterpret_cast<__half2*>(&u);
    return __half22float2(h);
}

// 4 pair-entries per thread: reads 5 source px x 3 ch, writes 4 x 16 B coalesced.
// PW = 228 = 4 * 57, so entry-quads never straddle a row.
__global__ __launch_bounds__(256)
void pack_kernel(const float* __restrict__ x)
{
    int t = blockIdx.x * blockDim.x + threadIdx.x;
    if (t >= NPAIR / 4) return;
    int e0  = t * 4;                  // first entry index
    int n   = e0 / (PH * PW);
    int rem = e0 - n * (PH * PW);
    int py  = rem / PW;
    int px0 = rem - py * PW;          // multiple of 4
    int y   = py - 2;

    // source x positions needed: x = px0-2 .. px0+2 (5 consecutive)
    float c0[5], c1[5], c2[5];
    bool yv = ((unsigned)y < (unsigned)H_);
    const float* img = x + (size_t)n * (C_ * H_ * W_) + (size_t)(yv ? y : 0) * W_;
#pragma unroll
    for (int i = 0; i < 5; i++) {
        int xs = px0 - 2 + i;
        bool v = yv && ((unsigned)xs < (unsigned)W_);
        c0[i] = v ? img[xs] : 0.0f;
        c1[i] = v ? img[xs + H_ * W_] : 0.0f;
        c2[i] = v ? img[xs + 2 * H_ * W_] : 0.0f;
    }

#pragma unroll
    for (int i = 0; i < 4; i++) {
        uint4 q;
        q.x = h2u(c0[i], c0[i + 1]);
        q.y = h2u(c1[i], c1[i + 1]);
        q.z = h2u(c2[i], c2[i + 1]);
        q.w = 0u;
        g_pair[e0 + i] = q;
    }
}

__global__ __launch_bounds__(THREADS)
void rot_bilinear_kernel(const float* __restrict__ thetas,
                         float* __restrict__ out)
{
    int w  = threadIdx.x;
    int b  = blockIdx.x;
    int hq = b % HQ;
    int ns = b / HQ;
    int n  = ns / S_;

    float theta = __ldg(&thetas[ns]);
    float sn, cs;
    __sincosf(theta, &sn, &cs);

    const float inv = 2.0f / 224.0f;
    int h0 = hq * HPT;

    // image-space source coords for (h0, w); per h-step: ix -= sn, iy += cs
    float xs = (w  + 0.5f) * inv - 1.0f;
    float ys = (h0 + 0.5f) * inv - 1.0f;
    float ix = fmaf(cs * xs - sn * ys, 112.0f, 111.5f);
    float iy = fmaf(sn * xs + cs * ys, 112.0f, 111.5f);

    const uint4* pair = g_pair + (size_t)n * (PH * PW);

    size_t obase = (size_t)ns * (C_ * H_ * W_) + (size_t)h0 * W_ + w;

    // corner-row cache: A = row iy0 pair, B = row iy0+1 pair
    uint4 A = make_uint4(0, 0, 0, 0);
    uint4 B = make_uint4(0, 0, 0, 0);
    int pcx = -1000000, pcy = -1000000;

#pragma unroll
    for (int r = 0; r < HPT; r++) {
        int ix0 = __float2int_rd(ix);
        int iy0 = __float2int_rd(iy);
        float wx1 = ix - (float)ix0;
        float wy1 = iy - (float)iy0;
        float wx0 = 1.0f - wx1;
        float wy0 = 1.0f - wy1;

        float w00 = wy0 * wx0;
        float w01 = wy0 * wx1;
        float w10 = wy1 * wx0;
        float w11 = wy1 * wx1;

        // clamp into padded apron (fully-OOB pixels read zero entries)
        int cx = min(max(ix0, -2), 224);
        int cy = min(max(iy0, -2), 224);

        int off = (cy + 2) * PW + (cx + 2);

        bool sx  = (cx == pcx);
        bool sy  = sx & (cy == pcy);       // both rows cached
        bool dy1 = sx & (cy == pcy + 1);   // A' = old B

        uint4 An = dy1 ? B : A;
        uint4 Bn = B;
        bool needA = !(sy | dy1);
        bool needB = !sy;
        if (needA) An = __ldg(pair + off);
        if (needB) Bn = __ldg(pair + off + PW);
        A = An;
        B = Bn;
        pcx = cx;
        pcy = cy;

        float2 a0 = u2f(A.x), a1 = u2f(A.y), a2 = u2f(A.z);
        float2 b0 = u2f(B.x), b1 = u2f(B.y), b2 = u2f(B.z);

        float v0 = a0.x * w00;
        v0 = fmaf(a0.y, w01, v0);
        v0 = fmaf(b0.x, w10, v0);
        v0 = fmaf(b0.y, w11, v0);

        float v1 = a1.x * w00;
        v1 = fmaf(a1.y, w01, v1);
        v1 = fmaf(b1.x, w10, v1);
        v1 = fmaf(b1.y, w11, v1);

        float v2 = a2.x * w00;
        v2 = fmaf(a2.y, w01, v2);
        v2 = fmaf(b2.x, w10, v2);
        v2 = fmaf(b2.y, w11, v2);

        // coalesced streaming stores (write-once output; keep pair grid in L2)
        __stcs(out + obase + (size_t)r * W_,               v0);
        __stcs(out + obase + (size_t)r * W_ + H_ * W_,     v1);
        __stcs(out + obase + (size_t)r * W_ + 2 * H_ * W_, v2);

        ix -= sn;
        iy += cs;
    }
}

extern "C" void kernel_launch(void* const* d_in, const int* in_sizes, int n_in,
                              void* d_out, int out_size)
{
    const float* x      = (const float*)d_in[0];
    const float* thetas = (const float*)d_in[1];
    float* out          = (float*)d_out;

    pack_kernel<<<(NPAIR / 4 + 255) / 256, 256>>>(x);
    rot_bilinear_kernel<<<NBLOCKS, THREADS>>>(thetas, out);
}